// round 5
// baseline (speedup 1.0000x reference)
#include <cuda_runtime.h>
#include <cuda_fp16.h>
#include <math.h>

#define N_NODES 100000
#define N_EDGES 1600000
#define N_GRAPHS 64
#define SLOPE 0.2f

// ---------------- scratch (device globals: allocation-free) ----------------
__device__ __half g_xlh[(size_t)N_NODES * 256];   // fp16 transformed features (both layers)
__device__ float g_h1[(size_t)N_NODES * 64];
__device__ float g_es[N_NODES * 4];
__device__ float g_ed[N_NODES * 4];
__device__ int   g_colsrc[N_EDGES];
__device__ int   g_cnt[N_NODES];
__device__ int   g_fill[N_NODES];
__device__ int   g_tmp[N_NODES];
__device__ int   g_rowptr[N_NODES + 1];
__device__ int   g_bsum[128];
__device__ int   g_boff[128];
__device__ float g_P1[24];
__device__ float g_P2[512];

// ---------------- prep ----------------
__global__ void k_zero(float* __restrict__ out) {
    int i = blockIdx.x * blockDim.x + threadIdx.x;
    if (i < N_NODES) { g_cnt[i] = 0; g_fill[i] = 0; }
    if (i < N_GRAPHS * 64) out[i] = 0.f;
}

__global__ void k_count(const int* __restrict__ ei) {
    int i = blockIdx.x * blockDim.x + threadIdx.x;
    if (i < N_EDGES) atomicAdd(&g_cnt[ei[N_EDGES + i]], 1);
}

__global__ void k_prep(const float* __restrict__ W1, const float* __restrict__ as1,
                       const float* __restrict__ ad1, const float* __restrict__ W2,
                       const float* __restrict__ as2, const float* __restrict__ ad2) {
    int t = threadIdx.x;  // 512
    {
        int k = t >> 3, r = t & 7, h = r >> 1;
        const float* a = (r & 1) ? ad2 : as2;
        float s = 0.f;
        #pragma unroll 8
        for (int c = 0; c < 64; c++) s += W2[k * 256 + h * 64 + c] * a[h * 64 + c];
        g_P2[t] = s;
    }
    if (t < 24) {
        int k = t >> 3, r = t & 7, h = r >> 1;
        const float* a = (r & 1) ? ad1 : as1;
        float s = 0.f;
        #pragma unroll 8
        for (int c = 0; c < 64; c++) s += W1[k * 256 + h * 64 + c] * a[h * 64 + c];
        g_P1[t] = s;
    }
}

// ---------------- scan ----------------
__global__ void k_scan1() {
    __shared__ int sd[1024];
    int t = threadIdx.x;
    int idx = blockIdx.x * 1024 + t;
    int v = (idx < N_NODES) ? g_cnt[idx] : 0;
    sd[t] = v;
    __syncthreads();
    for (int o = 1; o < 1024; o <<= 1) {
        int add = (t >= o) ? sd[t - o] : 0;
        __syncthreads();
        sd[t] += add;
        __syncthreads();
    }
    if (idx < N_NODES) g_tmp[idx] = sd[t];
    if (t == 1023) g_bsum[blockIdx.x] = sd[1023];
}

__global__ void k_scan2(int nblocks) {
    if (threadIdx.x == 0) {
        int run = 0;
        for (int b = 0; b < nblocks; b++) { g_boff[b] = run; run += g_bsum[b]; }
        g_rowptr[N_NODES] = N_EDGES;
    }
}

__global__ void k_scan3() {
    int i = blockIdx.x * blockDim.x + threadIdx.x;
    if (i < N_NODES) g_rowptr[i] = g_tmp[i] - g_cnt[i] + g_boff[i >> 10];
}

__global__ void k_fill(const int* __restrict__ ei) {
    int i = blockIdx.x * blockDim.x + threadIdx.x;
    if (i < N_EDGES) {
        int s = ei[i];
        int d = ei[N_EDGES + i];
        int pos = g_rowptr[d] + atomicAdd(&g_fill[d], 1);
        g_colsrc[pos] = s;
    }
}

// ---------------- pack helpers ----------------
__device__ __forceinline__ unsigned pack_h2(float a, float b) {
    __half2 h = __floats2half2_rn(a, b);
    return *(unsigned*)&h;
}
__device__ __forceinline__ float2 unpack_h2(unsigned u) {
    return __half22float2(*(__half2*)&u);
}

// ---------------- layer-1 transform (fp16 out) ----------------
__global__ void __launch_bounds__(256) k_xl1(const float* __restrict__ x, const float* __restrict__ W1) {
    __shared__ float w[768];
    for (int i = threadIdx.x; i < 768; i += 256) w[i] = W1[i];
    __syncthreads();
    int warp = (blockIdx.x * blockDim.x + threadIdx.x) >> 5;
    if (warp >= N_NODES) return;
    int lane = threadIdx.x & 31;
    float x0 = x[warp * 3 + 0], x1 = x[warp * 3 + 1], x2 = x[warp * 3 + 2];
    int c0 = lane * 8;
    float o[8];
    #pragma unroll
    for (int j = 0; j < 8; j++)
        o[j] = x0 * w[c0 + j] + x1 * w[256 + c0 + j] + x2 * w[512 + c0 + j];
    uint4 v;
    v.x = pack_h2(o[0], o[1]); v.y = pack_h2(o[2], o[3]);
    v.z = pack_h2(o[4], o[5]); v.w = pack_h2(o[6], o[7]);
    ((uint4*)(g_xlh + (size_t)warp * 256 + c0))[0] = v;
    if (lane < 8) {
        float t = x0 * g_P1[lane] + x1 * g_P1[8 + lane] + x2 * g_P1[16 + lane];
        int h = lane >> 1;
        if (lane & 1) g_ed[warp * 4 + h] = t;
        else          g_es[warp * 4 + h] = t;
    }
}

// ---------------- layer-2 transform: xl2 = h1 @ W2 (fp16 out) ----------------
__global__ void __launch_bounds__(256) k_gemm(const float* __restrict__ W) {
    __shared__ float ws[32 * 256];
    __shared__ float hs[32 * 64];
    int n0 = blockIdx.x * 64;
    int tid = threadIdx.x;
    int ty = tid >> 5, tx = tid & 31;
    float acc[8][8];
    #pragma unroll
    for (int i = 0; i < 8; i++)
        #pragma unroll
        for (int j = 0; j < 8; j++) acc[i][j] = 0.f;

    for (int k0 = 0; k0 < 64; k0 += 32) {
        __syncthreads();
        const float4* Wg = (const float4*)(W + k0 * 256);
        float4* wsv = (float4*)ws;
        #pragma unroll
        for (int i = 0; i < 8; i++) wsv[tid + i * 256] = Wg[tid + i * 256];
        #pragma unroll
        for (int i = 0; i < 2; i++) {
            int q = tid + i * 256;
            int n = q >> 3, k4 = q & 7;
            int node = n0 + n;
            float4 v = make_float4(0.f, 0.f, 0.f, 0.f);
            if (node < N_NODES) v = *(const float4*)(g_h1 + (size_t)node * 64 + k0 + k4 * 4);
            hs[(k4 * 4 + 0) * 64 + n] = v.x;
            hs[(k4 * 4 + 1) * 64 + n] = v.y;
            hs[(k4 * 4 + 2) * 64 + n] = v.z;
            hs[(k4 * 4 + 3) * 64 + n] = v.w;
        }
        __syncthreads();
        #pragma unroll
        for (int k = 0; k < 32; k++) {
            float4 a0 = *(float4*)&hs[k * 64 + ty * 8];
            float4 a1 = *(float4*)&hs[k * 64 + ty * 8 + 4];
            float4 b0 = *(float4*)&ws[k * 256 + tx * 4];
            float4 b1 = *(float4*)&ws[k * 256 + tx * 4 + 128];
            float a[8] = {a0.x, a0.y, a0.z, a0.w, a1.x, a1.y, a1.z, a1.w};
            float b[8] = {b0.x, b0.y, b0.z, b0.w, b1.x, b1.y, b1.z, b1.w};
            #pragma unroll
            for (int i = 0; i < 8; i++)
                #pragma unroll
                for (int j = 0; j < 8; j++) acc[i][j] += a[i] * b[j];
        }
    }
    #pragma unroll
    for (int i = 0; i < 8; i++) {
        int node = n0 + ty * 8 + i;
        if (node < N_NODES) {
            uint2 u0, u1;
            u0.x = pack_h2(acc[i][0], acc[i][1]); u0.y = pack_h2(acc[i][2], acc[i][3]);
            u1.x = pack_h2(acc[i][4], acc[i][5]); u1.y = pack_h2(acc[i][6], acc[i][7]);
            *(uint2*)(g_xlh + (size_t)node * 256 + tx * 4)       = u0;
            *(uint2*)(g_xlh + (size_t)node * 256 + tx * 4 + 128) = u1;
        }
    }
}

// ---------------- es2/ed2 = h1 @ P2 ----------------
__global__ void __launch_bounds__(256) k_es2() {
    __shared__ float p2[512];
    for (int i = threadIdx.x; i < 512; i += 256) p2[i] = g_P2[i];
    __syncthreads();
    int warp = (blockIdx.x * blockDim.x + threadIdx.x) >> 5;
    if (warp >= N_NODES) return;
    int lane = threadIdx.x & 31;
    int c0 = lane * 2;
    float v0 = g_h1[(size_t)warp * 64 + c0];
    float v1 = g_h1[(size_t)warp * 64 + c0 + 1];
    float acc[8];
    #pragma unroll
    for (int r = 0; r < 8; r++) acc[r] = v0 * p2[c0 * 8 + r] + v1 * p2[(c0 + 1) * 8 + r];
    #pragma unroll
    for (int o = 16; o; o >>= 1)
        #pragma unroll
        for (int r = 0; r < 8; r++) acc[r] += __shfl_xor_sync(0xffffffffu, acc[r], o);
    float v = acc[0];
    #pragma unroll
    for (int r = 1; r < 8; r++) if (lane == r) v = acc[r];
    if (lane < 8) {
        int h = lane >> 1;
        if (lane & 1) g_ed[warp * 4 + h] = v;
        else          g_es[warp * 4 + h] = v;
    }
}

// ---------------- GAT aggregation (warp per dst node) ----------------
// mode 0: write relu(mean+bias) to g_h1 ; mode 1: fused global-add-pool into pool
__global__ void __launch_bounds__(256) k_agg(const float* __restrict__ bias, int mode,
                                             const int* __restrict__ batch,
                                             float* __restrict__ pool) {
    int warp = (blockIdx.x * blockDim.x + threadIdx.x) >> 5;
    if (warp >= N_NODES) return;
    int lane = threadIdx.x & 31;
    int n = warp;
    int beg = g_rowptr[n], end = g_rowptr[n + 1];
    float4 edv = *(const float4*)(g_ed + n * 4);
    float ed0 = edv.x, ed1 = edv.y, ed2 = edv.z, ed3 = edv.w;

    // pass 1: per-head max over incoming edges
    float m0 = -1e30f, m1 = -1e30f, m2 = -1e30f, m3 = -1e30f;
    for (int e = beg + lane; e < end; e += 32) {
        int s = g_colsrc[e];
        float4 e4 = *(const float4*)(g_es + s * 4);
        float v;
        v = e4.x + ed0; v = v > 0.f ? v : SLOPE * v; m0 = fmaxf(m0, v);
        v = e4.y + ed1; v = v > 0.f ? v : SLOPE * v; m1 = fmaxf(m1, v);
        v = e4.z + ed2; v = v > 0.f ? v : SLOPE * v; m2 = fmaxf(m2, v);
        v = e4.w + ed3; v = v > 0.f ? v : SLOPE * v; m3 = fmaxf(m3, v);
    }
    #pragma unroll
    for (int o = 16; o; o >>= 1) {
        m0 = fmaxf(m0, __shfl_xor_sync(0xffffffffu, m0, o));
        m1 = fmaxf(m1, __shfl_xor_sync(0xffffffffu, m1, o));
        m2 = fmaxf(m2, __shfl_xor_sync(0xffffffffu, m2, o));
        m3 = fmaxf(m3, __shfl_xor_sync(0xffffffffu, m3, o));
    }

    int h = lane >> 3;
    float my_m  = (h == 0) ? m0 : (h == 1) ? m1 : (h == 2) ? m2 : m3;
    float my_ed = (h == 0) ? ed0 : (h == 1) ? ed1 : (h == 2) ? ed2 : ed3;

    // pass 2: 4-edge unrolled gather; all loads hoisted ahead of FMAs -> 4x MLP
    const uint4* xl4 = (const uint4*)g_xlh;     // row = 32 uint4 (512 B)
    float acc[8] = {0, 0, 0, 0, 0, 0, 0, 0};
    float ssum = 0.f;
    int e = beg;
    for (; e + 4 <= end; e += 4) {
        int s0 = g_colsrc[e + 0];
        int s1 = g_colsrc[e + 1];
        int s2 = g_colsrc[e + 2];
        int s3 = g_colsrc[e + 3];
        float l0 = g_es[s0 * 4 + h];
        float l1 = g_es[s1 * 4 + h];
        float l2 = g_es[s2 * 4 + h];
        float l3 = g_es[s3 * 4 + h];
        uint4 r0 = xl4[(size_t)s0 * 32 + lane];
        uint4 r1 = xl4[(size_t)s1 * 32 + lane];
        uint4 r2 = xl4[(size_t)s2 * 32 + lane];
        uint4 r3 = xl4[(size_t)s3 * 32 + lane];
        l0 += my_ed; l1 += my_ed; l2 += my_ed; l3 += my_ed;
        l0 = l0 > 0.f ? l0 : SLOPE * l0;
        l1 = l1 > 0.f ? l1 : SLOPE * l1;
        l2 = l2 > 0.f ? l2 : SLOPE * l2;
        l3 = l3 > 0.f ? l3 : SLOPE * l3;
        float w0 = __expf(l0 - my_m);
        float w1 = __expf(l1 - my_m);
        float w2 = __expf(l2 - my_m);
        float w3 = __expf(l3 - my_m);
        ssum += (w0 + w1) + (w2 + w3);
        float2 f;
        f = unpack_h2(r0.x); acc[0] += w0 * f.x; acc[1] += w0 * f.y;
        f = unpack_h2(r0.y); acc[2] += w0 * f.x; acc[3] += w0 * f.y;
        f = unpack_h2(r0.z); acc[4] += w0 * f.x; acc[5] += w0 * f.y;
        f = unpack_h2(r0.w); acc[6] += w0 * f.x; acc[7] += w0 * f.y;
        f = unpack_h2(r1.x); acc[0] += w1 * f.x; acc[1] += w1 * f.y;
        f = unpack_h2(r1.y); acc[2] += w1 * f.x; acc[3] += w1 * f.y;
        f = unpack_h2(r1.z); acc[4] += w1 * f.x; acc[5] += w1 * f.y;
        f = unpack_h2(r1.w); acc[6] += w1 * f.x; acc[7] += w1 * f.y;
        f = unpack_h2(r2.x); acc[0] += w2 * f.x; acc[1] += w2 * f.y;
        f = unpack_h2(r2.y); acc[2] += w2 * f.x; acc[3] += w2 * f.y;
        f = unpack_h2(r2.z); acc[4] += w2 * f.x; acc[5] += w2 * f.y;
        f = unpack_h2(r2.w); acc[6] += w2 * f.x; acc[7] += w2 * f.y;
        f = unpack_h2(r3.x); acc[0] += w3 * f.x; acc[1] += w3 * f.y;
        f = unpack_h2(r3.y); acc[2] += w3 * f.x; acc[3] += w3 * f.y;
        f = unpack_h2(r3.z); acc[4] += w3 * f.x; acc[5] += w3 * f.y;
        f = unpack_h2(r3.w); acc[6] += w3 * f.x; acc[7] += w3 * f.y;
    }
    for (; e < end; e++) {
        int s0 = g_colsrc[e];
        float l0 = g_es[s0 * 4 + h] + my_ed;
        uint4 r0 = xl4[(size_t)s0 * 32 + lane];
        l0 = l0 > 0.f ? l0 : SLOPE * l0;
        float w0 = __expf(l0 - my_m);
        ssum += w0;
        float2 f;
        f = unpack_h2(r0.x); acc[0] += w0 * f.x; acc[1] += w0 * f.y;
        f = unpack_h2(r0.y); acc[2] += w0 * f.x; acc[3] += w0 * f.y;
        f = unpack_h2(r0.z); acc[4] += w0 * f.x; acc[5] += w0 * f.y;
        f = unpack_h2(r0.w); acc[6] += w0 * f.x; acc[7] += w0 * f.y;
    }
    float inv = (end > beg) ? 1.f / ssum : 0.f;
    float r[8];
    #pragma unroll
    for (int j = 0; j < 8; j++) r[j] = acc[j] * inv;
    // head mean: lanes {L, L^8, L^16, L^24} hold matching within-head channels
    #pragma unroll
    for (int j = 0; j < 8; j++) {
        r[j] += __shfl_xor_sync(0xffffffffu, r[j], 8);
        r[j] += __shfl_xor_sync(0xffffffffu, r[j], 16);
    }
    int cc = (lane & 7) * 8;
    #pragma unroll
    for (int j = 0; j < 8; j++) {
        r[j] = 0.25f * r[j] + bias[cc + j];
        r[j] = fmaxf(r[j], 0.f);
    }
    if (mode == 1) {
        if (lane < 8) {
            int g = batch[n];
            #pragma unroll
            for (int j = 0; j < 8; j++) atomicAdd(&pool[g * 64 + cc + j], r[j]);
        }
    } else if (lane < 8) {
        float4* o = (float4*)(g_h1 + (size_t)n * 64 + cc);
        o[0] = make_float4(r[0], r[1], r[2], r[3]);
        o[1] = make_float4(r[4], r[5], r[6], r[7]);
    }
}

// ---------------- launch ----------------
extern "C" void kernel_launch(void* const* d_in, const int* in_sizes, int n_in,
                              void* d_out, int out_size) {
    const float* x     = (const float*)d_in[0];
    const int*   ei    = (const int*)d_in[1];     // int32 (JAX x64 disabled)
    const int*   batch = (const int*)d_in[2];     // int32
    const float* W1 = (const float*)d_in[3];
    const float* a_src1 = (const float*)d_in[4];
    const float* a_dst1 = (const float*)d_in[5];
    const float* b1 = (const float*)d_in[6];
    const float* W2 = (const float*)d_in[7];
    const float* a_src2 = (const float*)d_in[8];
    const float* a_dst2 = (const float*)d_in[9];
    const float* b2 = (const float*)d_in[10];
    float* out = (float*)d_out;

    const int NB_N  = (N_NODES + 255) / 256;
    const int NB_E  = (N_EDGES + 255) / 256;
    const int NB_W  = (N_NODES * 32 + 255) / 256;
    const int NB_S1 = (N_NODES + 1023) / 1024;
    const int NB_G  = (N_NODES + 63) / 64;

    k_zero<<<NB_N, 256>>>(out);
    k_count<<<NB_E, 256>>>(ei);
    k_prep<<<1, 512>>>(W1, a_src1, a_dst1, W2, a_src2, a_dst2);
    k_scan1<<<NB_S1, 1024>>>();
    k_scan2<<<1, 32>>>(NB_S1);
    k_scan3<<<NB_N, 256>>>();
    k_fill<<<NB_E, 256>>>(ei);

    // layer 1
    k_xl1<<<NB_W, 256>>>(x, W1);
    k_agg<<<NB_W, 256>>>(b1, 0, nullptr, nullptr);

    // layer 2
    k_gemm<<<NB_G, 256>>>(W2);
    k_es2<<<NB_W, 256>>>();
    k_agg<<<NB_W, 256>>>(b2, 1, batch, out);
}

// round 6
// speedup vs baseline: 3.1212x; 3.1212x over previous
#include <cuda_runtime.h>
#include <cuda_fp16.h>
#include <math.h>

#define N_NODES 100000
#define N_EDGES 1600000
#define N_GRAPHS 64
#define SLOPE 0.2f

// ---------------- scratch (device globals: allocation-free) ----------------
__device__ __half g_xlh[(size_t)N_NODES * 256];   // fp16 transformed features (both layers)
__device__ float g_h1[(size_t)N_NODES * 64];      // layer-1 output, then layer-2 output (in place)
__device__ float g_es[N_NODES * 4];
__device__ float g_ed[N_NODES * 4];
__device__ int   g_colsrc[N_EDGES];
__device__ int   g_cnt[N_NODES];
__device__ int   g_fill[N_NODES];
__device__ int   g_tmp[N_NODES];
__device__ int   g_rowptr[N_NODES + 1];
__device__ int   g_bsum[128];
__device__ int   g_boff[128];
__device__ float g_P1[24];
__device__ float g_P2[512];

// ---------------- prep ----------------
__global__ void k_zero(float* __restrict__ out) {
    int i = blockIdx.x * blockDim.x + threadIdx.x;
    if (i < N_NODES) { g_cnt[i] = 0; g_fill[i] = 0; }
    if (i < N_GRAPHS * 64) out[i] = 0.f;
}

__global__ void k_count(const int* __restrict__ ei) {
    int i = blockIdx.x * blockDim.x + threadIdx.x;
    if (i < N_EDGES) atomicAdd(&g_cnt[ei[N_EDGES + i]], 1);
}

__global__ void k_prep(const float* __restrict__ W1, const float* __restrict__ as1,
                       const float* __restrict__ ad1, const float* __restrict__ W2,
                       const float* __restrict__ as2, const float* __restrict__ ad2) {
    int t = threadIdx.x;  // 512
    {
        int k = t >> 3, r = t & 7, h = r >> 1;
        const float* a = (r & 1) ? ad2 : as2;
        float s = 0.f;
        #pragma unroll 8
        for (int c = 0; c < 64; c++) s += W2[k * 256 + h * 64 + c] * a[h * 64 + c];
        g_P2[t] = s;
    }
    if (t < 24) {
        int k = t >> 3, r = t & 7, h = r >> 1;
        const float* a = (r & 1) ? ad1 : as1;
        float s = 0.f;
        #pragma unroll 8
        for (int c = 0; c < 64; c++) s += W1[k * 256 + h * 64 + c] * a[h * 64 + c];
        g_P1[t] = s;
    }
}

// ---------------- scan ----------------
__global__ void k_scan1() {
    __shared__ int sd[1024];
    int t = threadIdx.x;
    int idx = blockIdx.x * 1024 + t;
    int v = (idx < N_NODES) ? g_cnt[idx] : 0;
    sd[t] = v;
    __syncthreads();
    for (int o = 1; o < 1024; o <<= 1) {
        int add = (t >= o) ? sd[t - o] : 0;
        __syncthreads();
        sd[t] += add;
        __syncthreads();
    }
    if (idx < N_NODES) g_tmp[idx] = sd[t];
    if (t == 1023) g_bsum[blockIdx.x] = sd[1023];
}

__global__ void k_scan2(int nblocks) {
    if (threadIdx.x == 0) {
        int run = 0;
        for (int b = 0; b < nblocks; b++) { g_boff[b] = run; run += g_bsum[b]; }
        g_rowptr[N_NODES] = N_EDGES;
    }
}

__global__ void k_scan3() {
    int i = blockIdx.x * blockDim.x + threadIdx.x;
    if (i < N_NODES) g_rowptr[i] = g_tmp[i] - g_cnt[i] + g_boff[i >> 10];
}

__global__ void k_fill(const int* __restrict__ ei) {
    int i = blockIdx.x * blockDim.x + threadIdx.x;
    if (i < N_EDGES) {
        int s = ei[i];
        int d = ei[N_EDGES + i];
        int pos = g_rowptr[d] + atomicAdd(&g_fill[d], 1);
        g_colsrc[pos] = s;
    }
}

// ---------------- pack helpers ----------------
__device__ __forceinline__ unsigned pack_h2(float a, float b) {
    __half2 h = __floats2half2_rn(a, b);
    return *(unsigned*)&h;
}
__device__ __forceinline__ float2 unpack_h2(unsigned u) {
    return __half22float2(*(__half2*)&u);
}

// ---------------- layer-1 transform (fp16 out) ----------------
__global__ void __launch_bounds__(256) k_xl1(const float* __restrict__ x, const float* __restrict__ W1) {
    __shared__ float w[768];
    for (int i = threadIdx.x; i < 768; i += 256) w[i] = W1[i];
    __syncthreads();
    int warp = (blockIdx.x * blockDim.x + threadIdx.x) >> 5;
    if (warp >= N_NODES) return;
    int lane = threadIdx.x & 31;
    float x0 = x[warp * 3 + 0], x1 = x[warp * 3 + 1], x2 = x[warp * 3 + 2];
    int c0 = lane * 8;
    float o[8];
    #pragma unroll
    for (int j = 0; j < 8; j++)
        o[j] = x0 * w[c0 + j] + x1 * w[256 + c0 + j] + x2 * w[512 + c0 + j];
    uint4 v;
    v.x = pack_h2(o[0], o[1]); v.y = pack_h2(o[2], o[3]);
    v.z = pack_h2(o[4], o[5]); v.w = pack_h2(o[6], o[7]);
    ((uint4*)(g_xlh + (size_t)warp * 256 + c0))[0] = v;
    if (lane < 8) {
        float t = x0 * g_P1[lane] + x1 * g_P1[8 + lane] + x2 * g_P1[16 + lane];
        int h = lane >> 1;
        if (lane & 1) g_ed[warp * 4 + h] = t;
        else          g_es[warp * 4 + h] = t;
    }
}

// ---------------- layer-2 transform: xl2 = h1 @ W2 (fp16 out) ----------------
__global__ void __launch_bounds__(256) k_gemm(const float* __restrict__ W) {
    __shared__ float ws[32 * 256];
    __shared__ float hs[32 * 64];
    int n0 = blockIdx.x * 64;
    int tid = threadIdx.x;
    int ty = tid >> 5, tx = tid & 31;
    float acc[8][8];
    #pragma unroll
    for (int i = 0; i < 8; i++)
        #pragma unroll
        for (int j = 0; j < 8; j++) acc[i][j] = 0.f;

    for (int k0 = 0; k0 < 64; k0 += 32) {
        __syncthreads();
        const float4* Wg = (const float4*)(W + k0 * 256);
        float4* wsv = (float4*)ws;
        #pragma unroll
        for (int i = 0; i < 8; i++) wsv[tid + i * 256] = Wg[tid + i * 256];
        #pragma unroll
        for (int i = 0; i < 2; i++) {
            int q = tid + i * 256;
            int n = q >> 3, k4 = q & 7;
            int node = n0 + n;
            float4 v = make_float4(0.f, 0.f, 0.f, 0.f);
            if (node < N_NODES) v = *(const float4*)(g_h1 + (size_t)node * 64 + k0 + k4 * 4);
            hs[(k4 * 4 + 0) * 64 + n] = v.x;
            hs[(k4 * 4 + 1) * 64 + n] = v.y;
            hs[(k4 * 4 + 2) * 64 + n] = v.z;
            hs[(k4 * 4 + 3) * 64 + n] = v.w;
        }
        __syncthreads();
        #pragma unroll
        for (int k = 0; k < 32; k++) {
            float4 a0 = *(float4*)&hs[k * 64 + ty * 8];
            float4 a1 = *(float4*)&hs[k * 64 + ty * 8 + 4];
            float4 b0 = *(float4*)&ws[k * 256 + tx * 4];
            float4 b1 = *(float4*)&ws[k * 256 + tx * 4 + 128];
            float a[8] = {a0.x, a0.y, a0.z, a0.w, a1.x, a1.y, a1.z, a1.w};
            float b[8] = {b0.x, b0.y, b0.z, b0.w, b1.x, b1.y, b1.z, b1.w};
            #pragma unroll
            for (int i = 0; i < 8; i++)
                #pragma unroll
                for (int j = 0; j < 8; j++) acc[i][j] += a[i] * b[j];
        }
    }
    #pragma unroll
    for (int i = 0; i < 8; i++) {
        int node = n0 + ty * 8 + i;
        if (node < N_NODES) {
            uint2 u0, u1;
            u0.x = pack_h2(acc[i][0], acc[i][1]); u0.y = pack_h2(acc[i][2], acc[i][3]);
            u1.x = pack_h2(acc[i][4], acc[i][5]); u1.y = pack_h2(acc[i][6], acc[i][7]);
            *(uint2*)(g_xlh + (size_t)node * 256 + tx * 4)       = u0;
            *(uint2*)(g_xlh + (size_t)node * 256 + tx * 4 + 128) = u1;
        }
    }
}

// ---------------- es2/ed2 = h1 @ P2 ----------------
__global__ void __launch_bounds__(256) k_es2() {
    __shared__ float p2[512];
    for (int i = threadIdx.x; i < 512; i += 256) p2[i] = g_P2[i];
    __syncthreads();
    int warp = (blockIdx.x * blockDim.x + threadIdx.x) >> 5;
    if (warp >= N_NODES) return;
    int lane = threadIdx.x & 31;
    int c0 = lane * 2;
    float v0 = g_h1[(size_t)warp * 64 + c0];
    float v1 = g_h1[(size_t)warp * 64 + c0 + 1];
    float acc[8];
    #pragma unroll
    for (int r = 0; r < 8; r++) acc[r] = v0 * p2[c0 * 8 + r] + v1 * p2[(c0 + 1) * 8 + r];
    #pragma unroll
    for (int o = 16; o; o >>= 1)
        #pragma unroll
        for (int r = 0; r < 8; r++) acc[r] += __shfl_xor_sync(0xffffffffu, acc[r], o);
    float v = acc[0];
    #pragma unroll
    for (int r = 1; r < 8; r++) if (lane == r) v = acc[r];
    if (lane < 8) {
        int h = lane >> 1;
        if (lane & 1) g_ed[warp * 4 + h] = v;
        else          g_es[warp * 4 + h] = v;
    }
}

// ---------------- GAT aggregation (warp per dst node), writes g_h1 ----------------
__global__ void __launch_bounds__(256) k_agg(const float* __restrict__ bias) {
    int warp = (blockIdx.x * blockDim.x + threadIdx.x) >> 5;
    if (warp >= N_NODES) return;
    int lane = threadIdx.x & 31;
    int n = warp;
    int beg = g_rowptr[n], end = g_rowptr[n + 1];
    float4 edv = *(const float4*)(g_ed + n * 4);
    float ed0 = edv.x, ed1 = edv.y, ed2 = edv.z, ed3 = edv.w;

    // pass 1: per-head max over incoming edges
    float m0 = -1e30f, m1 = -1e30f, m2 = -1e30f, m3 = -1e30f;
    for (int e = beg + lane; e < end; e += 32) {
        int s = g_colsrc[e];
        float4 e4 = *(const float4*)(g_es + s * 4);
        float v;
        v = e4.x + ed0; v = v > 0.f ? v : SLOPE * v; m0 = fmaxf(m0, v);
        v = e4.y + ed1; v = v > 0.f ? v : SLOPE * v; m1 = fmaxf(m1, v);
        v = e4.z + ed2; v = v > 0.f ? v : SLOPE * v; m2 = fmaxf(m2, v);
        v = e4.w + ed3; v = v > 0.f ? v : SLOPE * v; m3 = fmaxf(m3, v);
    }
    #pragma unroll
    for (int o = 16; o; o >>= 1) {
        m0 = fmaxf(m0, __shfl_xor_sync(0xffffffffu, m0, o));
        m1 = fmaxf(m1, __shfl_xor_sync(0xffffffffu, m1, o));
        m2 = fmaxf(m2, __shfl_xor_sync(0xffffffffu, m2, o));
        m3 = fmaxf(m3, __shfl_xor_sync(0xffffffffu, m3, o));
    }

    int h = lane >> 3;
    float my_m  = (h == 0) ? m0 : (h == 1) ? m1 : (h == 2) ? m2 : m3;
    float my_ed = (h == 0) ? ed0 : (h == 1) ? ed1 : (h == 2) ? ed2 : ed3;

    // pass 2: 2-edge unrolled gather; 1 x LDG.128 of fp16 per lane per edge
    const uint4* xl4 = (const uint4*)g_xlh;     // row = 32 uint4 (512 B)
    float acc[8] = {0, 0, 0, 0, 0, 0, 0, 0};
    float ssum = 0.f;
    int e = beg;
    for (; e + 2 <= end; e += 2) {
        int s0 = g_colsrc[e];
        int s1 = g_colsrc[e + 1];
        float v0 = g_es[s0 * 4 + h] + my_ed;
        float v1 = g_es[s1 * 4 + h] + my_ed;
        uint4 r0 = xl4[(size_t)s0 * 32 + lane];
        uint4 r1 = xl4[(size_t)s1 * 32 + lane];
        v0 = v0 > 0.f ? v0 : SLOPE * v0;
        v1 = v1 > 0.f ? v1 : SLOPE * v1;
        float w0 = __expf(v0 - my_m);
        float w1 = __expf(v1 - my_m);
        ssum += w0 + w1;
        float2 f;
        f = unpack_h2(r0.x); acc[0] += w0 * f.x; acc[1] += w0 * f.y;
        f = unpack_h2(r0.y); acc[2] += w0 * f.x; acc[3] += w0 * f.y;
        f = unpack_h2(r0.z); acc[4] += w0 * f.x; acc[5] += w0 * f.y;
        f = unpack_h2(r0.w); acc[6] += w0 * f.x; acc[7] += w0 * f.y;
        f = unpack_h2(r1.x); acc[0] += w1 * f.x; acc[1] += w1 * f.y;
        f = unpack_h2(r1.y); acc[2] += w1 * f.x; acc[3] += w1 * f.y;
        f = unpack_h2(r1.z); acc[4] += w1 * f.x; acc[5] += w1 * f.y;
        f = unpack_h2(r1.w); acc[6] += w1 * f.x; acc[7] += w1 * f.y;
    }
    if (e < end) {
        int s0 = g_colsrc[e];
        float v0 = g_es[s0 * 4 + h] + my_ed;
        uint4 r0 = xl4[(size_t)s0 * 32 + lane];
        v0 = v0 > 0.f ? v0 : SLOPE * v0;
        float w0 = __expf(v0 - my_m);
        ssum += w0;
        float2 f;
        f = unpack_h2(r0.x); acc[0] += w0 * f.x; acc[1] += w0 * f.y;
        f = unpack_h2(r0.y); acc[2] += w0 * f.x; acc[3] += w0 * f.y;
        f = unpack_h2(r0.z); acc[4] += w0 * f.x; acc[5] += w0 * f.y;
        f = unpack_h2(r0.w); acc[6] += w0 * f.x; acc[7] += w0 * f.y;
    }
    float inv = (end > beg) ? 1.f / ssum : 0.f;
    float r[8];
    #pragma unroll
    for (int j = 0; j < 8; j++) r[j] = acc[j] * inv;
    // head mean: lanes {L, L^8, L^16, L^24} hold matching within-head channels
    #pragma unroll
    for (int j = 0; j < 8; j++) {
        r[j] += __shfl_xor_sync(0xffffffffu, r[j], 8);
        r[j] += __shfl_xor_sync(0xffffffffu, r[j], 16);
    }
    int cc = (lane & 7) * 8;
    #pragma unroll
    for (int j = 0; j < 8; j++) {
        r[j] = 0.25f * r[j] + bias[cc + j];
        r[j] = fmaxf(r[j], 0.f);
    }
    if (lane < 8) {
        float4* o = (float4*)(g_h1 + (size_t)n * 64 + cc);
        o[0] = make_float4(r[0], r[1], r[2], r[3]);
        o[1] = make_float4(r[4], r[5], r[6], r[7]);
    }
}

// ---------------- global-add-pool: sorted-segment reduction, ~30K atomics ----------------
__global__ void __launch_bounds__(256) k_pool(const int* __restrict__ batch,
                                              float* __restrict__ out) {
    int t = threadIdx.x;
    int c = t & 63;              // channel owned by this thread
    int part = t >> 6;           // 0..3
    int n0 = blockIdx.x * 1024 + part * 256;
    int n1 = n0 + 256;
    if (n1 > N_NODES) n1 = N_NODES;
    float acc = 0.f;
    int cur = -1;
    for (int n = n0; n < n1; n++) {
        int g = batch[n];
        if (g != cur) {
            if (cur >= 0) atomicAdd(&out[cur * 64 + c], acc);
            cur = g;
            acc = 0.f;
        }
        acc += g_h1[(size_t)n * 64 + c];
    }
    if (cur >= 0) atomicAdd(&out[cur * 64 + c], acc);
}

// ---------------- launch ----------------
extern "C" void kernel_launch(void* const* d_in, const int* in_sizes, int n_in,
                              void* d_out, int out_size) {
    const float* x     = (const float*)d_in[0];
    const int*   ei    = (const int*)d_in[1];     // int32 (JAX x64 disabled)
    const int*   batch = (const int*)d_in[2];     // int32
    const float* W1 = (const float*)d_in[3];
    const float* a_src1 = (const float*)d_in[4];
    const float* a_dst1 = (const float*)d_in[5];
    const float* b1 = (const float*)d_in[6];
    const float* W2 = (const float*)d_in[7];
    const float* a_src2 = (const float*)d_in[8];
    const float* a_dst2 = (const float*)d_in[9];
    const float* b2 = (const float*)d_in[10];
    float* out = (float*)d_out;

    const int NB_N  = (N_NODES + 255) / 256;
    const int NB_E  = (N_EDGES + 255) / 256;
    const int NB_W  = (N_NODES * 32 + 255) / 256;
    const int NB_S1 = (N_NODES + 1023) / 1024;
    const int NB_G  = (N_NODES + 63) / 64;

    k_zero<<<NB_N, 256>>>(out);
    k_count<<<NB_E, 256>>>(ei);
    k_prep<<<1, 512>>>(W1, a_src1, a_dst1, W2, a_src2, a_dst2);
    k_scan1<<<NB_S1, 1024>>>();
    k_scan2<<<1, 32>>>(NB_S1);
    k_scan3<<<NB_N, 256>>>();
    k_fill<<<NB_E, 256>>>(ei);

    // layer 1
    k_xl1<<<NB_W, 256>>>(x, W1);
    k_agg<<<NB_W, 256>>>(b1);

    // layer 2
    k_gemm<<<NB_G, 256>>>(W2);
    k_es2<<<NB_W, 256>>>();
    k_agg<<<NB_W, 256>>>(b2);   // overwrites g_h1 with h2 (readers done)

    // pooled output
    k_pool<<<NB_S1, 256>>>(batch, out);
}

// round 7
// speedup vs baseline: 3.2462x; 1.0400x over previous
#include <cuda_runtime.h>
#include <cuda_fp16.h>
#include <math.h>

#define N_NODES 100000
#define N_EDGES 1600000
#define N_GRAPHS 64
#define SLOPE 0.2f

// ---------------- scratch (device globals: allocation-free) ----------------
__device__ __half g_xlh[(size_t)N_NODES * 256];   // fp16 transformed features (both layers)
__device__ float g_h1[(size_t)N_NODES * 64];      // layer-1 output, then layer-2 output (in place)
__device__ float g_es[N_NODES * 4];
__device__ float g_ed[N_NODES * 4];
__device__ int   g_colsrc[N_EDGES];
__device__ int   g_cnt[N_NODES];
__device__ int   g_fill[N_NODES];
__device__ int   g_tmp[N_NODES];
__device__ int   g_rowptr[N_NODES + 1];
__device__ int   g_bsum[128];
__device__ int   g_boff[128];
__device__ float g_P1[24];
__device__ float g_P2[512];

// ---------------- prep ----------------
__global__ void k_zero(float* __restrict__ out) {
    int i = blockIdx.x * blockDim.x + threadIdx.x;
    if (i < N_NODES) { g_cnt[i] = 0; g_fill[i] = 0; }
    if (i < N_GRAPHS * 64) out[i] = 0.f;
}

__global__ void k_count(const int* __restrict__ ei) {
    int i = blockIdx.x * blockDim.x + threadIdx.x;
    if (i < N_EDGES) atomicAdd(&g_cnt[ei[N_EDGES + i]], 1);
}

__global__ void k_prep(const float* __restrict__ W1, const float* __restrict__ as1,
                       const float* __restrict__ ad1, const float* __restrict__ W2,
                       const float* __restrict__ as2, const float* __restrict__ ad2) {
    int t = threadIdx.x;  // 512
    {
        int k = t >> 3, r = t & 7, h = r >> 1;
        const float* a = (r & 1) ? ad2 : as2;
        float s = 0.f;
        #pragma unroll 8
        for (int c = 0; c < 64; c++) s += W2[k * 256 + h * 64 + c] * a[h * 64 + c];
        g_P2[t] = s;
    }
    if (t < 24) {
        int k = t >> 3, r = t & 7, h = r >> 1;
        const float* a = (r & 1) ? ad1 : as1;
        float s = 0.f;
        #pragma unroll 8
        for (int c = 0; c < 64; c++) s += W1[k * 256 + h * 64 + c] * a[h * 64 + c];
        g_P1[t] = s;
    }
}

// ---------------- scan ----------------
__global__ void k_scan1() {
    __shared__ int sd[1024];
    int t = threadIdx.x;
    int idx = blockIdx.x * 1024 + t;
    int v = (idx < N_NODES) ? g_cnt[idx] : 0;
    sd[t] = v;
    __syncthreads();
    for (int o = 1; o < 1024; o <<= 1) {
        int add = (t >= o) ? sd[t - o] : 0;
        __syncthreads();
        sd[t] += add;
        __syncthreads();
    }
    if (idx < N_NODES) g_tmp[idx] = sd[t];
    if (t == 1023) g_bsum[blockIdx.x] = sd[1023];
}

__global__ void k_scan2(int nblocks) {
    if (threadIdx.x == 0) {
        int run = 0;
        for (int b = 0; b < nblocks; b++) { g_boff[b] = run; run += g_bsum[b]; }
        g_rowptr[N_NODES] = N_EDGES;
    }
}

__global__ void k_scan3() {
    int i = blockIdx.x * blockDim.x + threadIdx.x;
    if (i < N_NODES) g_rowptr[i] = g_tmp[i] - g_cnt[i] + g_boff[i >> 10];
}

__global__ void k_fill(const int* __restrict__ ei) {
    int i = blockIdx.x * blockDim.x + threadIdx.x;
    if (i < N_EDGES) {
        int s = ei[i];
        int d = ei[N_EDGES + i];
        int pos = g_rowptr[d] + atomicAdd(&g_fill[d], 1);
        g_colsrc[pos] = s;
    }
}

// ---------------- pack helpers ----------------
__device__ __forceinline__ unsigned pack_h2(float a, float b) {
    __half2 h = __floats2half2_rn(a, b);
    return *(unsigned*)&h;
}
__device__ __forceinline__ float2 unpack_h2(unsigned u) {
    return __half22float2(*(__half2*)&u);
}

// ---------------- layer-1 transform (fp16 out) ----------------
__global__ void __launch_bounds__(256) k_xl1(const float* __restrict__ x, const float* __restrict__ W1) {
    __shared__ float w[768];
    for (int i = threadIdx.x; i < 768; i += 256) w[i] = W1[i];
    __syncthreads();
    int warp = (blockIdx.x * blockDim.x + threadIdx.x) >> 5;
    if (warp >= N_NODES) return;
    int lane = threadIdx.x & 31;
    float x0 = x[warp * 3 + 0], x1 = x[warp * 3 + 1], x2 = x[warp * 3 + 2];
    int c0 = lane * 8;
    float o[8];
    #pragma unroll
    for (int j = 0; j < 8; j++)
        o[j] = x0 * w[c0 + j] + x1 * w[256 + c0 + j] + x2 * w[512 + c0 + j];
    uint4 v;
    v.x = pack_h2(o[0], o[1]); v.y = pack_h2(o[2], o[3]);
    v.z = pack_h2(o[4], o[5]); v.w = pack_h2(o[6], o[7]);
    ((uint4*)(g_xlh + (size_t)warp * 256 + c0))[0] = v;
    if (lane < 8) {
        float t = x0 * g_P1[lane] + x1 * g_P1[8 + lane] + x2 * g_P1[16 + lane];
        int h = lane >> 1;
        if (lane & 1) g_ed[warp * 4 + h] = t;
        else          g_es[warp * 4 + h] = t;
    }
}

// ---------------- layer-2 transform: xl2 = h1 @ W2 (fp16 out) ----------------
__global__ void __launch_bounds__(256) k_gemm(const float* __restrict__ W) {
    __shared__ float ws[32 * 256];
    __shared__ float hs[32 * 64];
    int n0 = blockIdx.x * 64;
    int tid = threadIdx.x;
    int ty = tid >> 5, tx = tid & 31;
    float acc[8][8];
    #pragma unroll
    for (int i = 0; i < 8; i++)
        #pragma unroll
        for (int j = 0; j < 8; j++) acc[i][j] = 0.f;

    for (int k0 = 0; k0 < 64; k0 += 32) {
        __syncthreads();
        const float4* Wg = (const float4*)(W + k0 * 256);
        float4* wsv = (float4*)ws;
        #pragma unroll
        for (int i = 0; i < 8; i++) wsv[tid + i * 256] = Wg[tid + i * 256];
        #pragma unroll
        for (int i = 0; i < 2; i++) {
            int q = tid + i * 256;
            int n = q >> 3, k4 = q & 7;
            int node = n0 + n;
            float4 v = make_float4(0.f, 0.f, 0.f, 0.f);
            if (node < N_NODES) v = *(const float4*)(g_h1 + (size_t)node * 64 + k0 + k4 * 4);
            hs[(k4 * 4 + 0) * 64 + n] = v.x;
            hs[(k4 * 4 + 1) * 64 + n] = v.y;
            hs[(k4 * 4 + 2) * 64 + n] = v.z;
            hs[(k4 * 4 + 3) * 64 + n] = v.w;
        }
        __syncthreads();
        #pragma unroll
        for (int k = 0; k < 32; k++) {
            float4 a0 = *(float4*)&hs[k * 64 + ty * 8];
            float4 a1 = *(float4*)&hs[k * 64 + ty * 8 + 4];
            float4 b0 = *(float4*)&ws[k * 256 + tx * 4];
            float4 b1 = *(float4*)&ws[k * 256 + tx * 4 + 128];
            float a[8] = {a0.x, a0.y, a0.z, a0.w, a1.x, a1.y, a1.z, a1.w};
            float b[8] = {b0.x, b0.y, b0.z, b0.w, b1.x, b1.y, b1.z, b1.w};
            #pragma unroll
            for (int i = 0; i < 8; i++)
                #pragma unroll
                for (int j = 0; j < 8; j++) acc[i][j] += a[i] * b[j];
        }
    }
    #pragma unroll
    for (int i = 0; i < 8; i++) {
        int node = n0 + ty * 8 + i;
        if (node < N_NODES) {
            uint2 u0, u1;
            u0.x = pack_h2(acc[i][0], acc[i][1]); u0.y = pack_h2(acc[i][2], acc[i][3]);
            u1.x = pack_h2(acc[i][4], acc[i][5]); u1.y = pack_h2(acc[i][6], acc[i][7]);
            *(uint2*)(g_xlh + (size_t)node * 256 + tx * 4)       = u0;
            *(uint2*)(g_xlh + (size_t)node * 256 + tx * 4 + 128) = u1;
        }
    }
}

// ---------------- es2/ed2 = h1 @ P2 ----------------
__global__ void __launch_bounds__(256) k_es2() {
    __shared__ float p2[512];
    for (int i = threadIdx.x; i < 512; i += 256) p2[i] = g_P2[i];
    __syncthreads();
    int warp = (blockIdx.x * blockDim.x + threadIdx.x) >> 5;
    if (warp >= N_NODES) return;
    int lane = threadIdx.x & 31;
    int c0 = lane * 2;
    float v0 = g_h1[(size_t)warp * 64 + c0];
    float v1 = g_h1[(size_t)warp * 64 + c0 + 1];
    float acc[8];
    #pragma unroll
    for (int r = 0; r < 8; r++) acc[r] = v0 * p2[c0 * 8 + r] + v1 * p2[(c0 + 1) * 8 + r];
    #pragma unroll
    for (int o = 16; o; o >>= 1)
        #pragma unroll
        for (int r = 0; r < 8; r++) acc[r] += __shfl_xor_sync(0xffffffffu, acc[r], o);
    float v = acc[0];
    #pragma unroll
    for (int r = 1; r < 8; r++) if (lane == r) v = acc[r];
    if (lane < 8) {
        int h = lane >> 1;
        if (lane & 1) g_ed[warp * 4 + h] = v;
        else          g_es[warp * 4 + h] = v;
    }
}

// ---------------- GAT aggregation (warp per dst node), single-pass softmax ----------------
// softmax computed WITHOUT max-shift (shift-invariant; logits are O(30) << 87).
// Clamp to +/-60 keeps exp finite and is bit-exact whenever |logit| < 60.
__global__ void __launch_bounds__(256) k_agg(const float* __restrict__ bias) {
    int warp = (blockIdx.x * blockDim.x + threadIdx.x) >> 5;
    if (warp >= N_NODES) return;
    int lane = threadIdx.x & 31;
    int n = warp;
    int beg = g_rowptr[n], end = g_rowptr[n + 1];
    int h = lane >> 3;
    float my_ed = g_ed[n * 4 + h];

    const uint4* xl4 = (const uint4*)g_xlh;     // row = 32 uint4 (512 B)
    float acc[8] = {0, 0, 0, 0, 0, 0, 0, 0};
    float ssum = 0.f;
    int e = beg;
    for (; e + 2 <= end; e += 2) {
        int s0 = g_colsrc[e];
        int s1 = g_colsrc[e + 1];
        float v0 = g_es[s0 * 4 + h] + my_ed;
        float v1 = g_es[s1 * 4 + h] + my_ed;
        uint4 r0 = xl4[(size_t)s0 * 32 + lane];
        uint4 r1 = xl4[(size_t)s1 * 32 + lane];
        v0 = v0 > 0.f ? v0 : SLOPE * v0;
        v1 = v1 > 0.f ? v1 : SLOPE * v1;
        v0 = fminf(fmaxf(v0, -60.f), 60.f);
        v1 = fminf(fmaxf(v1, -60.f), 60.f);
        float w0 = __expf(v0);
        float w1 = __expf(v1);
        ssum += w0 + w1;
        float2 f;
        f = unpack_h2(r0.x); acc[0] += w0 * f.x; acc[1] += w0 * f.y;
        f = unpack_h2(r0.y); acc[2] += w0 * f.x; acc[3] += w0 * f.y;
        f = unpack_h2(r0.z); acc[4] += w0 * f.x; acc[5] += w0 * f.y;
        f = unpack_h2(r0.w); acc[6] += w0 * f.x; acc[7] += w0 * f.y;
        f = unpack_h2(r1.x); acc[0] += w1 * f.x; acc[1] += w1 * f.y;
        f = unpack_h2(r1.y); acc[2] += w1 * f.x; acc[3] += w1 * f.y;
        f = unpack_h2(r1.z); acc[4] += w1 * f.x; acc[5] += w1 * f.y;
        f = unpack_h2(r1.w); acc[6] += w1 * f.x; acc[7] += w1 * f.y;
    }
    if (e < end) {
        int s0 = g_colsrc[e];
        float v0 = g_es[s0 * 4 + h] + my_ed;
        uint4 r0 = xl4[(size_t)s0 * 32 + lane];
        v0 = v0 > 0.f ? v0 : SLOPE * v0;
        v0 = fminf(fmaxf(v0, -60.f), 60.f);
        float w0 = __expf(v0);
        ssum += w0;
        float2 f;
        f = unpack_h2(r0.x); acc[0] += w0 * f.x; acc[1] += w0 * f.y;
        f = unpack_h2(r0.y); acc[2] += w0 * f.x; acc[3] += w0 * f.y;
        f = unpack_h2(r0.z); acc[4] += w0 * f.x; acc[5] += w0 * f.y;
        f = unpack_h2(r0.w); acc[6] += w0 * f.x; acc[7] += w0 * f.y;
    }
    float inv = (end > beg) ? 1.f / ssum : 0.f;
    float r[8];
    #pragma unroll
    for (int j = 0; j < 8; j++) r[j] = acc[j] * inv;
    // head mean: lanes {L, L^8, L^16, L^24} hold matching within-head channels
    #pragma unroll
    for (int j = 0; j < 8; j++) {
        r[j] += __shfl_xor_sync(0xffffffffu, r[j], 8);
        r[j] += __shfl_xor_sync(0xffffffffu, r[j], 16);
    }
    int cc = (lane & 7) * 8;
    #pragma unroll
    for (int j = 0; j < 8; j++) {
        r[j] = 0.25f * r[j] + bias[cc + j];
        r[j] = fmaxf(r[j], 0.f);
    }
    if (lane < 8) {
        float4* o = (float4*)(g_h1 + (size_t)n * 64 + cc);
        o[0] = make_float4(r[0], r[1], r[2], r[3]);
        o[1] = make_float4(r[4], r[5], r[6], r[7]);
    }
}

// ---------------- global-add-pool: sorted-segment reduction, ~30K atomics ----------------
__global__ void __launch_bounds__(256) k_pool(const int* __restrict__ batch,
                                              float* __restrict__ out) {
    int t = threadIdx.x;
    int c = t & 63;              // channel owned by this thread
    int part = t >> 6;           // 0..3
    int n0 = blockIdx.x * 1024 + part * 256;
    int n1 = n0 + 256;
    if (n1 > N_NODES) n1 = N_NODES;
    float acc = 0.f;
    int cur = -1;
    for (int n = n0; n < n1; n++) {
        int g = batch[n];
        if (g != cur) {
            if (cur >= 0) atomicAdd(&out[cur * 64 + c], acc);
            cur = g;
            acc = 0.f;
        }
        acc += g_h1[(size_t)n * 64 + c];
    }
    if (cur >= 0) atomicAdd(&out[cur * 64 + c], acc);
}

// ---------------- launch ----------------
extern "C" void kernel_launch(void* const* d_in, const int* in_sizes, int n_in,
                              void* d_out, int out_size) {
    const float* x     = (const float*)d_in[0];
    const int*   ei    = (const int*)d_in[1];     // int32 (JAX x64 disabled)
    const int*   batch = (const int*)d_in[2];     // int32
    const float* W1 = (const float*)d_in[3];
    const float* a_src1 = (const float*)d_in[4];
    const float* a_dst1 = (const float*)d_in[5];
    const float* b1 = (const float*)d_in[6];
    const float* W2 = (const float*)d_in[7];
    const float* a_src2 = (const float*)d_in[8];
    const float* a_dst2 = (const float*)d_in[9];
    const float* b2 = (const float*)d_in[10];
    float* out = (float*)d_out;

    const int NB_N  = (N_NODES + 255) / 256;
    const int NB_E  = (N_EDGES + 255) / 256;
    const int NB_W  = (N_NODES * 32 + 255) / 256;
    const int NB_S1 = (N_NODES + 1023) / 1024;
    const int NB_G  = (N_NODES + 63) / 64;

    k_zero<<<NB_N, 256>>>(out);
    k_count<<<NB_E, 256>>>(ei);
    k_prep<<<1, 512>>>(W1, a_src1, a_dst1, W2, a_src2, a_dst2);
    k_scan1<<<NB_S1, 1024>>>();
    k_scan2<<<1, 32>>>(NB_S1);
    k_scan3<<<NB_N, 256>>>();
    k_fill<<<NB_E, 256>>>(ei);

    // layer 1
    k_xl1<<<NB_W, 256>>>(x, W1);
    k_agg<<<NB_W, 256>>>(b1);

    // layer 2
    k_gemm<<<NB_G, 256>>>(W2);
    k_es2<<<NB_W, 256>>>();
    k_agg<<<NB_W, 256>>>(b2);   // overwrites g_h1 with h2 (readers done)

    // pooled output
    k_pool<<<NB_S1, 256>>>(batch, out);
}

// round 8
// speedup vs baseline: 4.5045x; 1.3876x over previous
#include <cuda_runtime.h>
#include <cuda_fp16.h>
#include <math.h>

#define N_NODES 100000
#define N_EDGES 1600000
#define N_GRAPHS 64
#define SLOPE 0.2f

// ---------------- scratch (device globals: allocation-free) ----------------
__device__ __half g_h1h[(size_t)N_NODES * 64];    // layer-1 output, fp16
__device__ __half g_Ah[(size_t)N_NODES * 256];    // layer-2 aggregated per-head features, fp16
__device__ float  g_h2[(size_t)N_NODES * 64];     // layer-2 output (pool input)
__device__ float  g_es[N_NODES * 4];
__device__ float  g_ed[N_NODES * 4];
__device__ float  g_es2[N_NODES * 4];
__device__ float  g_ed2[N_NODES * 4];
__device__ int    g_colsrc[N_EDGES];
__device__ int    g_cnt[N_NODES];
__device__ int    g_fill[N_NODES];
__device__ int    g_tmp[N_NODES];
__device__ int    g_rowptr[N_NODES + 1];
__device__ int    g_bsum[128];
__device__ int    g_boff[128];
__device__ float  g_P1[24];
__device__ float  g_P2[512];
__device__ __half g_W2f[64 * 256];   // [c][kk] = 0.25 * W2[k, h*64+c], kk = h*64+k (col-major B)

// ---------------- prep ----------------
__global__ void k_zero(float* __restrict__ out) {
    int i = blockIdx.x * blockDim.x + threadIdx.x;
    if (i < N_NODES) { g_cnt[i] = 0; g_fill[i] = 0; }
    if (i < N_GRAPHS * 64) out[i] = 0.f;
}

__global__ void k_count(const int* __restrict__ ei) {
    int i = blockIdx.x * blockDim.x + threadIdx.x;
    if (i < N_EDGES) atomicAdd(&g_cnt[ei[N_EDGES + i]], 1);
}

__global__ void k_prep(const float* __restrict__ W1, const float* __restrict__ as1,
                       const float* __restrict__ ad1, const float* __restrict__ W2,
                       const float* __restrict__ as2, const float* __restrict__ ad2) {
    int t = threadIdx.x;  // 512
    {
        int k = t >> 3, r = t & 7, h = r >> 1;
        const float* a = (r & 1) ? ad2 : as2;
        float s = 0.f;
        #pragma unroll 8
        for (int c = 0; c < 64; c++) s += W2[k * 256 + h * 64 + c] * a[h * 64 + c];
        g_P2[t] = s;
    }
    if (t < 24) {
        int k = t >> 3, r = t & 7, h = r >> 1;
        const float* a = (r & 1) ? ad1 : as1;
        float s = 0.f;
        #pragma unroll 8
        for (int c = 0; c < 64; c++) s += W1[k * 256 + h * 64 + c] * a[h * 64 + c];
        g_P1[t] = s;
    }
    // fold head-mean (0.25) into W2f; layout: g_W2f[c*256 + h*64 + k] = 0.25*W2[k, h*64+c]
    for (int idx = t; idx < 16384; idx += 512) {
        int c = idx >> 8, kk = idx & 255;
        int h = kk >> 6, k = kk & 63;
        g_W2f[idx] = __float2half(0.25f * W2[k * 256 + h * 64 + c]);
    }
}

// ---------------- scan ----------------
__global__ void k_scan1() {
    __shared__ int sd[1024];
    int t = threadIdx.x;
    int idx = blockIdx.x * 1024 + t;
    int v = (idx < N_NODES) ? g_cnt[idx] : 0;
    sd[t] = v;
    __syncthreads();
    for (int o = 1; o < 1024; o <<= 1) {
        int add = (t >= o) ? sd[t - o] : 0;
        __syncthreads();
        sd[t] += add;
        __syncthreads();
    }
    if (idx < N_NODES) g_tmp[idx] = sd[t];
    if (t == 1023) g_bsum[blockIdx.x] = sd[1023];
}

__global__ void k_scan2(int nblocks) {
    if (threadIdx.x == 0) {
        int run = 0;
        for (int b = 0; b < nblocks; b++) { g_boff[b] = run; run += g_bsum[b]; }
        g_rowptr[N_NODES] = N_EDGES;
    }
}

__global__ void k_scan3() {
    int i = blockIdx.x * blockDim.x + threadIdx.x;
    if (i < N_NODES) g_rowptr[i] = g_tmp[i] - g_cnt[i] + g_boff[i >> 10];
}

__global__ void k_fill(const int* __restrict__ ei) {
    int i = blockIdx.x * blockDim.x + threadIdx.x;
    if (i < N_EDGES) {
        int s = ei[i];
        int d = ei[N_EDGES + i];
        int pos = g_rowptr[d] + atomicAdd(&g_fill[d], 1);
        g_colsrc[pos] = s;
    }
}

// ---------------- pack helpers ----------------
__device__ __forceinline__ unsigned pack_h2(float a, float b) {
    __half2 h = __floats2half2_rn(a, b);
    return *(unsigned*)&h;
}
__device__ __forceinline__ float2 unpack_h2(unsigned u) {
    return __half22float2(*(__half2*)&u);
}

// ---------------- layer-1 logits: es1/ed1 = x @ P1 ----------------
__global__ void k_xled(const float* __restrict__ x) {
    int n = blockIdx.x * blockDim.x + threadIdx.x;
    if (n >= N_NODES) return;
    float x0 = x[n * 3 + 0], x1 = x[n * 3 + 1], x2 = x[n * 3 + 2];
    #pragma unroll
    for (int r = 0; r < 8; r++) {
        float v = x0 * g_P1[r] + x1 * g_P1[8 + r] + x2 * g_P1[16 + r];
        int h = r >> 1;
        if (r & 1) g_ed[n * 4 + h] = v;
        else       g_es[n * 4 + h] = v;
    }
}

// ---------------- layer 1, fully fused (warp per node) ----------------
// Gathers raw x[src] (12 B/edge), builds per-head A1[h,0:3], then
// h1 = relu(b1 + 0.25*sum_h A1n[h]@W1_h), es2/ed2 = h1@P2, h1 stored fp16.
__global__ void __launch_bounds__(256) k_l1(const float* __restrict__ x,
                                            const float* __restrict__ W1,
                                            const float* __restrict__ b1) {
    __shared__ float w1s[768];
    __shared__ float p2s[512];
    __shared__ float sAn[8][13];
    for (int i = threadIdx.x; i < 768; i += 256) w1s[i] = W1[i];
    for (int i = threadIdx.x; i < 512; i += 256) p2s[i] = g_P2[i];
    __syncthreads();
    int warp = (blockIdx.x * blockDim.x + threadIdx.x) >> 5;
    if (warp >= N_NODES) return;
    int lane = threadIdx.x & 31;
    int wid = threadIdx.x >> 5;
    int n = warp;
    int h = lane >> 3, kp = lane & 7;
    float my_ed = g_ed[n * 4 + h];
    int beg = g_rowptr[n], end = g_rowptr[n + 1];

    float acc = 0.f, ssum = 0.f;
    int e = beg;
    for (; e + 2 <= end; e += 2) {
        int s0 = g_colsrc[e], s1 = g_colsrc[e + 1];
        float v0 = g_es[s0 * 4 + h] + my_ed;
        float v1 = g_es[s1 * 4 + h] + my_ed;
        float xa = (kp < 3) ? x[s0 * 3 + kp] : 0.f;
        float xb = (kp < 3) ? x[s1 * 3 + kp] : 0.f;
        v0 = v0 > 0.f ? v0 : SLOPE * v0;
        v1 = v1 > 0.f ? v1 : SLOPE * v1;
        v0 = fminf(fmaxf(v0, -60.f), 60.f);
        v1 = fminf(fmaxf(v1, -60.f), 60.f);
        float w0 = __expf(v0), w1 = __expf(v1);
        ssum += w0 + w1;
        acc += w0 * xa + w1 * xb;
    }
    if (e < end) {
        int s0 = g_colsrc[e];
        float v0 = g_es[s0 * 4 + h] + my_ed;
        float xa = (kp < 3) ? x[s0 * 3 + kp] : 0.f;
        v0 = v0 > 0.f ? v0 : SLOPE * v0;
        v0 = fminf(fmaxf(v0, -60.f), 60.f);
        float w0 = __expf(v0);
        ssum += w0;
        acc += w0 * xa;
    }
    float inv = (end > beg) ? 1.f / ssum : 0.f;
    if (kp < 3) sAn[wid][h * 3 + kp] = acc * inv;
    __syncwarp();

    // h1 channels c0, c0+1 for this lane
    int c0 = lane * 2;
    float r0 = b1[c0], r1 = b1[c0 + 1];
    #pragma unroll
    for (int hh = 0; hh < 4; hh++)
        #pragma unroll
        for (int k = 0; k < 3; k++) {
            float a = sAn[wid][hh * 3 + k];
            r0 += 0.25f * a * w1s[k * 256 + hh * 64 + c0];
            r1 += 0.25f * a * w1s[k * 256 + hh * 64 + c0 + 1];
        }
    r0 = fmaxf(r0, 0.f);
    r1 = fmaxf(r1, 0.f);
    *(unsigned*)(g_h1h + (size_t)n * 64 + c0) = pack_h2(r0, r1);

    // layer-2 logits from h1 (fused k_es2)
    float ar[8];
    #pragma unroll
    for (int r = 0; r < 8; r++) ar[r] = r0 * p2s[c0 * 8 + r] + r1 * p2s[(c0 + 1) * 8 + r];
    #pragma unroll
    for (int o = 16; o; o >>= 1)
        #pragma unroll
        for (int r = 0; r < 8; r++) ar[r] += __shfl_xor_sync(0xffffffffu, ar[r], o);
    float v = ar[0];
    #pragma unroll
    for (int r = 1; r < 8; r++) if (lane == r) v = ar[r];
    if (lane < 8) {
        int hh = lane >> 1;
        if (lane & 1) g_ed2[n * 4 + hh] = v;
        else          g_es2[n * 4 + hh] = v;
    }
}

// ---------------- layer-2 aggregation (warp per node): A2[h,k] from h1h ----------------
__global__ void __launch_bounds__(256) k_agg2() {
    int warp = (blockIdx.x * blockDim.x + threadIdx.x) >> 5;
    if (warp >= N_NODES) return;
    int lane = threadIdx.x & 31;
    int n = warp;
    int h = lane >> 3, kp = lane & 7;
    float my_ed = g_ed2[n * 4 + h];
    int beg = g_rowptr[n], end = g_rowptr[n + 1];

    const uint4* h14 = (const uint4*)g_h1h;   // node row = 8 uint4 (128 B)
    float acc[8] = {0, 0, 0, 0, 0, 0, 0, 0};
    float ssum = 0.f;
    int e = beg;
    for (; e + 2 <= end; e += 2) {
        int s0 = g_colsrc[e], s1 = g_colsrc[e + 1];
        float v0 = g_es2[s0 * 4 + h] + my_ed;
        float v1 = g_es2[s1 * 4 + h] + my_ed;
        uint4 r0 = h14[(size_t)s0 * 8 + kp];
        uint4 r1 = h14[(size_t)s1 * 8 + kp];
        v0 = v0 > 0.f ? v0 : SLOPE * v0;
        v1 = v1 > 0.f ? v1 : SLOPE * v1;
        v0 = fminf(fmaxf(v0, -60.f), 60.f);
        v1 = fminf(fmaxf(v1, -60.f), 60.f);
        float w0 = __expf(v0), w1 = __expf(v1);
        ssum += w0 + w1;
        float2 f;
        f = unpack_h2(r0.x); acc[0] += w0 * f.x; acc[1] += w0 * f.y;
        f = unpack_h2(r0.y); acc[2] += w0 * f.x; acc[3] += w0 * f.y;
        f = unpack_h2(r0.z); acc[4] += w0 * f.x; acc[5] += w0 * f.y;
        f = unpack_h2(r0.w); acc[6] += w0 * f.x; acc[7] += w0 * f.y;
        f = unpack_h2(r1.x); acc[0] += w1 * f.x; acc[1] += w1 * f.y;
        f = unpack_h2(r1.y); acc[2] += w1 * f.x; acc[3] += w1 * f.y;
        f = unpack_h2(r1.z); acc[4] += w1 * f.x; acc[5] += w1 * f.y;
        f = unpack_h2(r1.w); acc[6] += w1 * f.x; acc[7] += w1 * f.y;
    }
    if (e < end) {
        int s0 = g_colsrc[e];
        float v0 = g_es2[s0 * 4 + h] + my_ed;
        uint4 r0 = h14[(size_t)s0 * 8 + kp];
        v0 = v0 > 0.f ? v0 : SLOPE * v0;
        v0 = fminf(fmaxf(v0, -60.f), 60.f);
        float w0 = __expf(v0);
        ssum += w0;
        float2 f;
        f = unpack_h2(r0.x); acc[0] += w0 * f.x; acc[1] += w0 * f.y;
        f = unpack_h2(r0.y); acc[2] += w0 * f.x; acc[3] += w0 * f.y;
        f = unpack_h2(r0.z); acc[4] += w0 * f.x; acc[5] += w0 * f.y;
        f = unpack_h2(r0.w); acc[6] += w0 * f.x; acc[7] += w0 * f.y;
    }
    float inv = (end > beg) ? 1.f / ssum : 0.f;
    uint4 o;
    o.x = pack_h2(acc[0] * inv, acc[1] * inv);
    o.y = pack_h2(acc[2] * inv, acc[3] * inv);
    o.z = pack_h2(acc[4] * inv, acc[5] * inv);
    o.w = pack_h2(acc[6] * inv, acc[7] * inv);
    // kk = lane*8 + j = h*64 + (kp*8+j)
    *(uint4*)(g_Ah + (size_t)n * 256 + lane * 8) = o;
}

// ---------------- output GEMM via HMMA: h2 = relu(A2 @ W2f + b2) ----------------
// M=100000, K=256, N=64; A fp16 row-major, B fp16 col-major; m16n8k16 fragments.
__global__ void __launch_bounds__(256) k_out(const float* __restrict__ b2) {
    __shared__ __half sA[128 * 72];   // [m][k-chunk] padded
    __shared__ __half sB[64 * 72];    // [n][k-chunk] padded (col-major B)
    int n0 = blockIdx.x * 128;
    int tid = threadIdx.x, wid = tid >> 5, lane = tid & 31;
    int g = lane >> 2, tg = lane & 3;
    float acc[8][4];
    #pragma unroll
    for (int i = 0; i < 8; i++)
        #pragma unroll
        for (int j = 0; j < 4; j++) acc[i][j] = 0.f;

    for (int kc = 0; kc < 4; kc++) {
        int k0 = kc * 64;
        __syncthreads();
        #pragma unroll
        for (int i = 0; i < 4; i++) {           // A: 128 rows x 8 uint4
            int q = tid + i * 256;
            int r = q >> 3, u = q & 7;
            int node = n0 + r;
            uint4 v = make_uint4(0, 0, 0, 0);
            if (node < N_NODES) v = *(const uint4*)(g_Ah + (size_t)node * 256 + k0 + u * 8);
            *(uint4*)(sA + r * 72 + u * 8) = v;
        }
        #pragma unroll
        for (int i = 0; i < 2; i++) {           // B: 64 cols x 8 uint4
            int q = tid + i * 256;
            int c = q >> 3, u = q & 7;
            *(uint4*)(sB + c * 72 + u * 8) = *(const uint4*)(g_W2f + c * 256 + k0 + u * 8);
        }
        __syncthreads();
        #pragma unroll
        for (int ks = 0; ks < 4; ks++) {
            int k1 = ks * 16;
            int arow = wid * 16 + g;
            unsigned a0 = *(unsigned*)(sA + arow * 72 + k1 + tg * 2);
            unsigned a1 = *(unsigned*)(sA + (arow + 8) * 72 + k1 + tg * 2);
            unsigned a2 = *(unsigned*)(sA + arow * 72 + k1 + 8 + tg * 2);
            unsigned a3 = *(unsigned*)(sA + (arow + 8) * 72 + k1 + 8 + tg * 2);
            #pragma unroll
            for (int nt = 0; nt < 8; nt++) {
                unsigned b0 = *(unsigned*)(sB + (nt * 8 + g) * 72 + k1 + tg * 2);
                unsigned b1 = *(unsigned*)(sB + (nt * 8 + g) * 72 + k1 + 8 + tg * 2);
                asm volatile(
                    "mma.sync.aligned.m16n8k16.row.col.f32.f16.f16.f32 "
                    "{%0,%1,%2,%3}, {%4,%5,%6,%7}, {%8,%9}, {%0,%1,%2,%3};\n"
                    : "+f"(acc[nt][0]), "+f"(acc[nt][1]), "+f"(acc[nt][2]), "+f"(acc[nt][3])
                    : "r"(a0), "r"(a1), "r"(a2), "r"(a3), "r"(b0), "r"(b1));
            }
        }
    }
    int row0 = n0 + wid * 16 + g;
    #pragma unroll
    for (int nt = 0; nt < 8; nt++) {
        int c = nt * 8 + tg * 2;
        float bb0 = b2[c], bb1 = b2[c + 1];
        if (row0 < N_NODES) {
            g_h2[(size_t)row0 * 64 + c]     = fmaxf(acc[nt][0] + bb0, 0.f);
            g_h2[(size_t)row0 * 64 + c + 1] = fmaxf(acc[nt][1] + bb1, 0.f);
        }
        if (row0 + 8 < N_NODES) {
            g_h2[(size_t)(row0 + 8) * 64 + c]     = fmaxf(acc[nt][2] + bb0, 0.f);
            g_h2[(size_t)(row0 + 8) * 64 + c + 1] = fmaxf(acc[nt][3] + bb1, 0.f);
        }
    }
}

// ---------------- global-add-pool: sorted-segment reduction ----------------
__global__ void __launch_bounds__(256) k_pool(const int* __restrict__ batch,
                                              float* __restrict__ out) {
    int t = threadIdx.x;
    int c = t & 63;
    int part = t >> 6;
    int n0 = blockIdx.x * 1024 + part * 256;
    int n1 = n0 + 256;
    if (n1 > N_NODES) n1 = N_NODES;
    float acc = 0.f;
    int cur = -1;
    for (int n = n0; n < n1; n++) {
        int g = batch[n];
        if (g != cur) {
            if (cur >= 0) atomicAdd(&out[cur * 64 + c], acc);
            cur = g;
            acc = 0.f;
        }
        acc += g_h2[(size_t)n * 64 + c];
    }
    if (cur >= 0) atomicAdd(&out[cur * 64 + c], acc);
}

// ---------------- launch ----------------
extern "C" void kernel_launch(void* const* d_in, const int* in_sizes, int n_in,
                              void* d_out, int out_size) {
    const float* x     = (const float*)d_in[0];
    const int*   ei    = (const int*)d_in[1];
    const int*   batch = (const int*)d_in[2];
    const float* W1 = (const float*)d_in[3];
    const float* a_src1 = (const float*)d_in[4];
    const float* a_dst1 = (const float*)d_in[5];
    const float* b1 = (const float*)d_in[6];
    const float* W2 = (const float*)d_in[7];
    const float* a_src2 = (const float*)d_in[8];
    const float* a_dst2 = (const float*)d_in[9];
    const float* b2 = (const float*)d_in[10];
    float* out = (float*)d_out;

    const int NB_N  = (N_NODES + 255) / 256;
    const int NB_E  = (N_EDGES + 255) / 256;
    const int NB_W  = (N_NODES * 32 + 255) / 256;
    const int NB_S1 = (N_NODES + 1023) / 1024;
    const int NB_O  = (N_NODES + 127) / 128;

    k_zero<<<NB_N, 256>>>(out);
    k_count<<<NB_E, 256>>>(ei);
    k_prep<<<1, 512>>>(W1, a_src1, a_dst1, W2, a_src2, a_dst2);
    k_scan1<<<NB_S1, 1024>>>();
    k_scan2<<<1, 32>>>(NB_S1);
    k_scan3<<<NB_N, 256>>>();
    k_fill<<<NB_E, 256>>>(ei);

    k_xled<<<NB_N, 256>>>(x);
    k_l1<<<NB_W, 256>>>(x, W1, b1);      // fused: agg1 + W1 + bias/relu + es2/ed2 + h1 fp16
    k_agg2<<<NB_W, 256>>>();             // A2 gather (128 B/edge)
    k_out<<<NB_O, 256>>>(b2);            // HMMA GEMM + bias + relu
    k_pool<<<NB_S1, 256>>>(batch, out);
}

// round 9
// speedup vs baseline: 4.5773x; 1.0162x over previous
#include <cuda_runtime.h>
#include <cuda_fp16.h>
#include <math.h>

#define N_NODES 100000
#define N_EDGES 1600000
#define N_GRAPHS 64
#define SLOPE 0.2f

// ---------------- scratch (device globals: allocation-free) ----------------
__device__ __half g_h1h[(size_t)N_NODES * 64];    // layer-1 output, fp16
__device__ __half g_Ah[(size_t)N_NODES * 256];    // layer-2 aggregated per-head features, fp16
__device__ float  g_h2[(size_t)N_NODES * 64];     // layer-2 output (pool input)
__device__ float  g_es[N_NODES * 4];
__device__ float  g_ed[N_NODES * 4];
__device__ float  g_es2[N_NODES * 4];
__device__ float  g_ed2[N_NODES * 4];
__device__ int    g_colsrc[N_EDGES];
__device__ int    g_cnt[N_NODES];
__device__ int    g_fill[N_NODES];
__device__ int    g_tmp[N_NODES];
__device__ int    g_rowptr[N_NODES + 1];
__device__ int    g_bsum[128];
__device__ int    g_boff[128];
__device__ float  g_P1[24];
__device__ float  g_P2[512];
__device__ __half g_W2f[64 * 256];   // [c][kk] = 0.25 * W2[k, h*64+c]

// ---------------- prep ----------------
__global__ void k_zero(float* __restrict__ out) {
    int i = blockIdx.x * blockDim.x + threadIdx.x;
    if (i < N_NODES) { g_cnt[i] = 0; g_fill[i] = 0; }
    if (i < N_GRAPHS * 64) out[i] = 0.f;
}

__global__ void k_count(const int* __restrict__ ei) {
    int i = blockIdx.x * blockDim.x + threadIdx.x;
    if (i < N_EDGES) atomicAdd(&g_cnt[ei[N_EDGES + i]], 1);
}

// grid 33 x 512: block 0 -> P1 + P2 ; blocks 1..32 -> W2f copy (parallel)
__global__ void k_prep(const float* __restrict__ W1, const float* __restrict__ as1,
                       const float* __restrict__ ad1, const float* __restrict__ W2,
                       const float* __restrict__ as2, const float* __restrict__ ad2) {
    int t = threadIdx.x;
    if (blockIdx.x == 0) {
        {
            int k = t >> 3, r = t & 7, h = r >> 1;
            const float* a = (r & 1) ? ad2 : as2;
            float s = 0.f;
            #pragma unroll 8
            for (int c = 0; c < 64; c++) s += W2[k * 256 + h * 64 + c] * a[h * 64 + c];
            g_P2[t] = s;
        }
        if (t < 24) {
            int k = t >> 3, r = t & 7, h = r >> 1;
            const float* a = (r & 1) ? ad1 : as1;
            float s = 0.f;
            #pragma unroll 8
            for (int c = 0; c < 64; c++) s += W1[k * 256 + h * 64 + c] * a[h * 64 + c];
            g_P1[t] = s;
        }
    } else {
        int idx = (blockIdx.x - 1) * 512 + t;   // 16384 entries
        int c = idx >> 8, kk = idx & 255;
        int h = kk >> 6, k = kk & 63;
        g_W2f[idx] = __float2half(0.25f * W2[k * 256 + h * 64 + c]);
    }
}

// ---------------- scan ----------------
__global__ void k_scan1() {
    __shared__ int sd[1024];
    int t = threadIdx.x;
    int idx = blockIdx.x * 1024 + t;
    int v = (idx < N_NODES) ? g_cnt[idx] : 0;
    sd[t] = v;
    __syncthreads();
    for (int o = 1; o < 1024; o <<= 1) {
        int add = (t >= o) ? sd[t - o] : 0;
        __syncthreads();
        sd[t] += add;
        __syncthreads();
    }
    if (idx < N_NODES) g_tmp[idx] = sd[t];
    if (t == 1023) g_bsum[blockIdx.x] = sd[1023];
}

__global__ void k_scan2(int nblocks) {
    if (threadIdx.x == 0) {
        int run = 0;
        for (int b = 0; b < nblocks; b++) { g_boff[b] = run; run += g_bsum[b]; }
        g_rowptr[N_NODES] = N_EDGES;
    }
}

// scan3 fused with layer-1 logits (es1/ed1 = x @ P1)
__global__ void k_scan3x(const float* __restrict__ x) {
    int i = blockIdx.x * blockDim.x + threadIdx.x;
    if (i >= N_NODES) return;
    g_rowptr[i] = g_tmp[i] - g_cnt[i] + g_boff[i >> 10];
    float x0 = x[i * 3 + 0], x1 = x[i * 3 + 1], x2 = x[i * 3 + 2];
    #pragma unroll
    for (int r = 0; r < 8; r++) {
        float v = x0 * g_P1[r] + x1 * g_P1[8 + r] + x2 * g_P1[16 + r];
        int h = r >> 1;
        if (r & 1) g_ed[i * 4 + h] = v;
        else       g_es[i * 4 + h] = v;
    }
}

__global__ void k_fill(const int* __restrict__ ei) {
    int i = blockIdx.x * blockDim.x + threadIdx.x;
    if (i < N_EDGES) {
        int s = ei[i];
        int d = ei[N_EDGES + i];
        int pos = g_rowptr[d] + atomicAdd(&g_fill[d], 1);
        g_colsrc[pos] = s;
    }
}

// ---------------- pack helpers ----------------
__device__ __forceinline__ unsigned pack_h2(float a, float b) {
    __half2 h = __floats2half2_rn(a, b);
    return *(unsigned*)&h;
}
__device__ __forceinline__ float2 unpack_h2(unsigned u) {
    return __half22float2(*(__half2*)&u);
}

// ---------------- layer 1, fully fused (warp per node), pipelined indices ----------------
__global__ void __launch_bounds__(256) k_l1(const float* __restrict__ x,
                                            const float* __restrict__ W1,
                                            const float* __restrict__ b1) {
    __shared__ float w1s[768];
    __shared__ float p2s[512];
    __shared__ float sAn[8][13];
    for (int i = threadIdx.x; i < 768; i += 256) w1s[i] = W1[i];
    for (int i = threadIdx.x; i < 512; i += 256) p2s[i] = g_P2[i];
    __syncthreads();
    int warp = (blockIdx.x * blockDim.x + threadIdx.x) >> 5;
    if (warp >= N_NODES) return;
    int lane = threadIdx.x & 31;
    int wid = threadIdx.x >> 5;
    int n = warp;
    int h = lane >> 3, kp = lane & 7;
    float my_ed = g_ed[n * 4 + h];
    int beg = g_rowptr[n], end = g_rowptr[n + 1];

    float acc = 0.f, ssum = 0.f;
    int e = beg;
    int s0 = 0, s1 = 0;
    if (e + 2 <= end) { s0 = g_colsrc[e]; s1 = g_colsrc[e + 1]; }
    while (e + 2 <= end) {
        int t0 = s0, t1 = s1;
        int en = e + 2;
        if (en + 2 <= end) { s0 = g_colsrc[en]; s1 = g_colsrc[en + 1]; }
        float v0 = g_es[t0 * 4 + h] + my_ed;
        float v1 = g_es[t1 * 4 + h] + my_ed;
        float xa = (kp < 3) ? x[t0 * 3 + kp] : 0.f;
        float xb = (kp < 3) ? x[t1 * 3 + kp] : 0.f;
        v0 = v0 > 0.f ? v0 : SLOPE * v0;
        v1 = v1 > 0.f ? v1 : SLOPE * v1;
        v0 = fminf(fmaxf(v0, -60.f), 60.f);
        v1 = fminf(fmaxf(v1, -60.f), 60.f);
        float w0 = __expf(v0), w1 = __expf(v1);
        ssum += w0 + w1;
        acc += w0 * xa + w1 * xb;
        e = en;
    }
    if (e < end) {
        int t0 = g_colsrc[e];
        float v0 = g_es[t0 * 4 + h] + my_ed;
        float xa = (kp < 3) ? x[t0 * 3 + kp] : 0.f;
        v0 = v0 > 0.f ? v0 : SLOPE * v0;
        v0 = fminf(fmaxf(v0, -60.f), 60.f);
        float w0 = __expf(v0);
        ssum += w0;
        acc += w0 * xa;
    }
    float inv = (end > beg) ? 1.f / ssum : 0.f;
    if (kp < 3) sAn[wid][h * 3 + kp] = acc * inv;
    __syncwarp();

    int c0 = lane * 2;
    float r0 = b1[c0], r1 = b1[c0 + 1];
    #pragma unroll
    for (int hh = 0; hh < 4; hh++)
        #pragma unroll
        for (int k = 0; k < 3; k++) {
            float a = sAn[wid][hh * 3 + k];
            r0 += 0.25f * a * w1s[k * 256 + hh * 64 + c0];
            r1 += 0.25f * a * w1s[k * 256 + hh * 64 + c0 + 1];
        }
    r0 = fmaxf(r0, 0.f);
    r1 = fmaxf(r1, 0.f);
    *(unsigned*)(g_h1h + (size_t)n * 64 + c0) = pack_h2(r0, r1);

    float ar[8];
    #pragma unroll
    for (int r = 0; r < 8; r++) ar[r] = r0 * p2s[c0 * 8 + r] + r1 * p2s[(c0 + 1) * 8 + r];
    #pragma unroll
    for (int o = 16; o; o >>= 1)
        #pragma unroll
        for (int r = 0; r < 8; r++) ar[r] += __shfl_xor_sync(0xffffffffu, ar[r], o);
    float v = ar[0];
    #pragma unroll
    for (int r = 1; r < 8; r++) if (lane == r) v = ar[r];
    if (lane < 8) {
        int hh = lane >> 1;
        if (lane & 1) g_ed2[n * 4 + hh] = v;
        else          g_es2[n * 4 + hh] = v;
    }
}

// ---------------- layer-2 aggregation (warp per node), pipelined indices ----------------
__global__ void __launch_bounds__(256) k_agg2() {
    int warp = (blockIdx.x * blockDim.x + threadIdx.x) >> 5;
    if (warp >= N_NODES) return;
    int lane = threadIdx.x & 31;
    int n = warp;
    int h = lane >> 3, kp = lane & 7;
    float my_ed = g_ed2[n * 4 + h];
    int beg = g_rowptr[n], end = g_rowptr[n + 1];

    const uint4* h14 = (const uint4*)g_h1h;   // node row = 8 uint4 (128 B)
    float acc[8] = {0, 0, 0, 0, 0, 0, 0, 0};
    float ssum = 0.f;
    int e = beg;
    int s0 = 0, s1 = 0;
    if (e + 2 <= end) { s0 = g_colsrc[e]; s1 = g_colsrc[e + 1]; }
    while (e + 2 <= end) {
        int t0 = s0, t1 = s1;
        int en = e + 2;
        if (en + 2 <= end) { s0 = g_colsrc[en]; s1 = g_colsrc[en + 1]; }
        float v0 = g_es2[t0 * 4 + h] + my_ed;
        float v1 = g_es2[t1 * 4 + h] + my_ed;
        uint4 r0 = h14[(size_t)t0 * 8 + kp];
        uint4 r1 = h14[(size_t)t1 * 8 + kp];
        v0 = v0 > 0.f ? v0 : SLOPE * v0;
        v1 = v1 > 0.f ? v1 : SLOPE * v1;
        v0 = fminf(fmaxf(v0, -60.f), 60.f);
        v1 = fminf(fmaxf(v1, -60.f), 60.f);
        float w0 = __expf(v0), w1 = __expf(v1);
        ssum += w0 + w1;
        float2 f;
        f = unpack_h2(r0.x); acc[0] += w0 * f.x; acc[1] += w0 * f.y;
        f = unpack_h2(r0.y); acc[2] += w0 * f.x; acc[3] += w0 * f.y;
        f = unpack_h2(r0.z); acc[4] += w0 * f.x; acc[5] += w0 * f.y;
        f = unpack_h2(r0.w); acc[6] += w0 * f.x; acc[7] += w0 * f.y;
        f = unpack_h2(r1.x); acc[0] += w1 * f.x; acc[1] += w1 * f.y;
        f = unpack_h2(r1.y); acc[2] += w1 * f.x; acc[3] += w1 * f.y;
        f = unpack_h2(r1.z); acc[4] += w1 * f.x; acc[5] += w1 * f.y;
        f = unpack_h2(r1.w); acc[6] += w1 * f.x; acc[7] += w1 * f.y;
        e = en;
    }
    if (e < end) {
        int t0 = g_colsrc[e];
        float v0 = g_es2[t0 * 4 + h] + my_ed;
        uint4 r0 = h14[(size_t)t0 * 8 + kp];
        v0 = v0 > 0.f ? v0 : SLOPE * v0;
        v0 = fminf(fmaxf(v0, -60.f), 60.f);
        float w0 = __expf(v0);
        ssum += w0;
        float2 f;
        f = unpack_h2(r0.x); acc[0] += w0 * f.x; acc[1] += w0 * f.y;
        f = unpack_h2(r0.y); acc[2] += w0 * f.x; acc[3] += w0 * f.y;
        f = unpack_h2(r0.z); acc[4] += w0 * f.x; acc[5] += w0 * f.y;
        f = unpack_h2(r0.w); acc[6] += w0 * f.x; acc[7] += w0 * f.y;
    }
    float inv = (end > beg) ? 1.f / ssum : 0.f;
    uint4 o;
    o.x = pack_h2(acc[0] * inv, acc[1] * inv);
    o.y = pack_h2(acc[2] * inv, acc[3] * inv);
    o.z = pack_h2(acc[4] * inv, acc[5] * inv);
    o.w = pack_h2(acc[6] * inv, acc[7] * inv);
    *(uint4*)(g_Ah + (size_t)n * 256 + lane * 8) = o;
}

// ---------------- output GEMM via HMMA: h2 = relu(A2 @ W2f + b2) ----------------
__global__ void __launch_bounds__(256) k_out(const float* __restrict__ b2) {
    __shared__ __half sA[128 * 72];
    __shared__ __half sB[64 * 72];
    int n0 = blockIdx.x * 128;
    int tid = threadIdx.x, wid = tid >> 5, lane = tid & 31;
    int g = lane >> 2, tg = lane & 3;
    float acc[8][4];
    #pragma unroll
    for (int i = 0; i < 8; i++)
        #pragma unroll
        for (int j = 0; j < 4; j++) acc[i][j] = 0.f;

    for (int kc = 0; kc < 4; kc++) {
        int k0 = kc * 64;
        __syncthreads();
        #pragma unroll
        for (int i = 0; i < 4; i++) {
            int q = tid + i * 256;
            int r = q >> 3, u = q & 7;
            int node = n0 + r;
            uint4 v = make_uint4(0, 0, 0, 0);
            if (node < N_NODES) v = *(const uint4*)(g_Ah + (size_t)node * 256 + k0 + u * 8);
            *(uint4*)(sA + r * 72 + u * 8) = v;
        }
        #pragma unroll
        for (int i = 0; i < 2; i++) {
            int q = tid + i * 256;
            int c = q >> 3, u = q & 7;
            *(uint4*)(sB + c * 72 + u * 8) = *(const uint4*)(g_W2f + c * 256 + k0 + u * 8);
        }
        __syncthreads();
        #pragma unroll
        for (int ks = 0; ks < 4; ks++) {
            int k1 = ks * 16;
            int arow = wid * 16 + g;
            unsigned a0 = *(unsigned*)(sA + arow * 72 + k1 + tg * 2);
            unsigned a1 = *(unsigned*)(sA + (arow + 8) * 72 + k1 + tg * 2);
            unsigned a2 = *(unsigned*)(sA + arow * 72 + k1 + 8 + tg * 2);
            unsigned a3 = *(unsigned*)(sA + (arow + 8) * 72 + k1 + 8 + tg * 2);
            #pragma unroll
            for (int nt = 0; nt < 8; nt++) {
                unsigned b0 = *(unsigned*)(sB + (nt * 8 + g) * 72 + k1 + tg * 2);
                unsigned b1 = *(unsigned*)(sB + (nt * 8 + g) * 72 + k1 + 8 + tg * 2);
                asm volatile(
                    "mma.sync.aligned.m16n8k16.row.col.f32.f16.f16.f32 "
                    "{%0,%1,%2,%3}, {%4,%5,%6,%7}, {%8,%9}, {%0,%1,%2,%3};\n"
                    : "+f"(acc[nt][0]), "+f"(acc[nt][1]), "+f"(acc[nt][2]), "+f"(acc[nt][3])
                    : "r"(a0), "r"(a1), "r"(a2), "r"(a3), "r"(b0), "r"(b1));
            }
        }
    }
    int row0 = n0 + wid * 16 + g;
    #pragma unroll
    for (int nt = 0; nt < 8; nt++) {
        int c = nt * 8 + tg * 2;
        float bb0 = b2[c], bb1 = b2[c + 1];
        if (row0 < N_NODES) {
            g_h2[(size_t)row0 * 64 + c]     = fmaxf(acc[nt][0] + bb0, 0.f);
            g_h2[(size_t)row0 * 64 + c + 1] = fmaxf(acc[nt][1] + bb1, 0.f);
        }
        if (row0 + 8 < N_NODES) {
            g_h2[(size_t)(row0 + 8) * 64 + c]     = fmaxf(acc[nt][2] + bb0, 0.f);
            g_h2[(size_t)(row0 + 8) * 64 + c + 1] = fmaxf(acc[nt][3] + bb1, 0.f);
        }
    }
}

// ---------------- global-add-pool: sorted-segment reduction ----------------
__global__ void __launch_bounds__(256) k_pool(const int* __restrict__ batch,
                                              float* __restrict__ out) {
    int t = threadIdx.x;
    int c = t & 63;
    int part = t >> 6;
    int n0 = blockIdx.x * 1024 + part * 256;
    int n1 = n0 + 256;
    if (n1 > N_NODES) n1 = N_NODES;
    float acc = 0.f;
    int cur = -1;
    for (int n = n0; n < n1; n++) {
        int g = batch[n];
        if (g != cur) {
            if (cur >= 0) atomicAdd(&out[cur * 64 + c], acc);
            cur = g;
            acc = 0.f;
        }
        acc += g_h2[(size_t)n * 64 + c];
    }
    if (cur >= 0) atomicAdd(&out[cur * 64 + c], acc);
}

// ---------------- launch ----------------
extern "C" void kernel_launch(void* const* d_in, const int* in_sizes, int n_in,
                              void* d_out, int out_size) {
    const float* x     = (const float*)d_in[0];
    const int*   ei    = (const int*)d_in[1];
    const int*   batch = (const int*)d_in[2];
    const float* W1 = (const float*)d_in[3];
    const float* a_src1 = (const float*)d_in[4];
    const float* a_dst1 = (const float*)d_in[5];
    const float* b1 = (const float*)d_in[6];
    const float* W2 = (const float*)d_in[7];
    const float* a_src2 = (const float*)d_in[8];
    const float* a_dst2 = (const float*)d_in[9];
    const float* b2 = (const float*)d_in[10];
    float* out = (float*)d_out;

    const int NB_N  = (N_NODES + 255) / 256;
    const int NB_E  = (N_EDGES + 255) / 256;
    const int NB_W  = (N_NODES * 32 + 255) / 256;
    const int NB_S1 = (N_NODES + 1023) / 1024;
    const int NB_O  = (N_NODES + 127) / 128;

    k_zero<<<NB_N, 256>>>(out);
    k_count<<<NB_E, 256>>>(ei);
    k_prep<<<33, 512>>>(W1, a_src1, a_dst1, W2, a_src2, a_dst2);
    k_scan1<<<NB_S1, 1024>>>();
    k_scan2<<<1, 32>>>(NB_S1);
    k_scan3x<<<NB_N, 256>>>(x);
    k_fill<<<NB_E, 256>>>(ei);

    k_l1<<<NB_W, 256>>>(x, W1, b1);
    k_agg2<<<NB_W, 256>>>();
    k_out<<<NB_O, 256>>>(b2);
    k_pool<<<NB_S1, 256>>>(batch, out);
}